// round 3
// baseline (speedup 1.0000x reference)
#include <cuda_runtime.h>

#define D_MODEL 768
#define SEQ     2048
#define BATCH   2
#define NHEAD   12
#define DK      64
#define MTOT    (BATCH*SEQ)   /* 4096 */

// Scratch (no cudaMalloc allowed)
__device__ float g_Q[MTOT * D_MODEL];
__device__ float g_K[MTOT * D_MODEL];
__device__ float g_V[MTOT * D_MODEL];
__device__ float g_ctx[MTOT * D_MODEL];

// ---------------------------------------------------------------------------
// helpers
// ---------------------------------------------------------------------------
__device__ __forceinline__ unsigned f2tf(float x) {
    unsigned r;
    asm("cvt.rna.tf32.f32 %0, %1;" : "=r"(r) : "f"(x));
    return r;
}

// D += A*B  (m16n8k8, A row-major, B col-major, tf32 in, f32 accum)
__device__ __forceinline__ void mma_tf32(float d[4], const unsigned a[4], const unsigned b[2]) {
    asm volatile(
        "mma.sync.aligned.m16n8k8.row.col.f32.tf32.tf32.f32 "
        "{%0,%1,%2,%3},{%4,%5,%6,%7},{%8,%9},{%0,%1,%2,%3};"
        : "+f"(d[0]), "+f"(d[1]), "+f"(d[2]), "+f"(d[3])
        : "r"(a[0]), "r"(a[1]), "r"(a[2]), "r"(a[3]),
          "r"(b[0]), "r"(b[1]));
}

__device__ __forceinline__ void cp16(void* dst, const void* src) {
    unsigned d = (unsigned)__cvta_generic_to_shared(dst);
    asm volatile("cp.async.cg.shared.global [%0], [%1], 16;\n" :: "r"(d), "l"(src));
}
__device__ __forceinline__ void cp_commit() {
    asm volatile("cp.async.commit_group;\n" ::: "memory");
}
template <int N>
__device__ __forceinline__ void cp_wait() {
    asm volatile("cp.async.wait_group %0;\n" :: "n"(N) : "memory");
}

extern __shared__ unsigned char dynsm[];

// ---------------------------------------------------------------------------
// GEMM: C[M,N] = A[M,768] @ W[N,768]^T, tile 128x128x32, 8 warps,
// cp.async double-buffered (fp32 in smem, tf32 cvt at fragment load).
// ---------------------------------------------------------------------------
#define GPAD 36
#define GBUF (128 * GPAD)
#define GEMM_SMEM_BYTES (4 * GBUF * 4)   /* 2 bufs x (A+W) = 73728 B */

__device__ __forceinline__ void gemm_stage(float* Ad, float* Wd,
                                           const float* __restrict__ A,
                                           const float* __restrict__ W,
                                           int bm, int bn, int k0, int tid)
{
#pragma unroll
    for (int u = 0; u < 4; u++) {
        int idx = tid + (u << 8);
        int r = idx >> 3;
        int c = (idx & 7) << 2;
        cp16(&Ad[r * GPAD + c], A + (size_t)(bm + r) * D_MODEL + k0 + c);
        cp16(&Wd[r * GPAD + c], W + (size_t)(bn + r) * D_MODEL + k0 + c);
    }
    cp_commit();
}

__device__ __forceinline__ void gemm_tf32(const float* __restrict__ A,
                                          const float* __restrict__ W,
                                          float* __restrict__ C)
{
    float* As = (float*)dynsm;            // 2 x 128 x GPAD
    float* Ws = (float*)dynsm + 2 * GBUF; // 2 x 128 x GPAD

    const int tid  = threadIdx.x;
    const int lane = tid & 31;
    const int warp = tid >> 5;
    const int wm   = (warp >> 2) * 64;
    const int wn   = (warp & 3) * 32;
    const int bm   = blockIdx.y * 128;
    const int bn   = blockIdx.x * 128;

    float acc[4][4][4];
#pragma unroll
    for (int mi = 0; mi < 4; mi++)
#pragma unroll
        for (int ni = 0; ni < 4; ni++)
#pragma unroll
            for (int r = 0; r < 4; r++) acc[mi][ni][r] = 0.0f;

    gemm_stage(As, Ws, A, W, bm, bn, 0, tid);

    const int NT = D_MODEL / 32;   // 24
    for (int t = 0; t < NT; t++) {
        cp_wait<0>();
        __syncthreads();
        if (t + 1 < NT)
            gemm_stage(As + ((t + 1) & 1) * GBUF, Ws + ((t + 1) & 1) * GBUF,
                       A, W, bm, bn, (t + 1) * 32, tid);

        const float* Ab = As + (t & 1) * GBUF;
        const float* Wb = Ws + (t & 1) * GBUF;

#pragma unroll
        for (int ks = 0; ks < 4; ks++) {
            const int kk = (ks << 3) + (lane & 3);
            unsigned a[4][4], b[4][2];
#pragma unroll
            for (int mi = 0; mi < 4; mi++) {
                int row = wm + (mi << 4) + (lane >> 2);
                a[mi][0] = f2tf(Ab[row * GPAD + kk]);
                a[mi][1] = f2tf(Ab[(row + 8) * GPAD + kk]);
                a[mi][2] = f2tf(Ab[row * GPAD + kk + 4]);
                a[mi][3] = f2tf(Ab[(row + 8) * GPAD + kk + 4]);
            }
#pragma unroll
            for (int ni = 0; ni < 4; ni++) {
                int col = wn + (ni << 3) + (lane >> 2);
                b[ni][0] = f2tf(Wb[col * GPAD + kk]);
                b[ni][1] = f2tf(Wb[col * GPAD + kk + 4]);
            }
#pragma unroll
            for (int mi = 0; mi < 4; mi++)
#pragma unroll
                for (int ni = 0; ni < 4; ni++)
                    mma_tf32(acc[mi][ni], a[mi], b[ni]);
        }
    }

#pragma unroll
    for (int mi = 0; mi < 4; mi++) {
#pragma unroll
        for (int ni = 0; ni < 4; ni++) {
            int row = bm + wm + (mi << 4) + (lane >> 2);
            int col = bn + wn + (ni << 3) + ((lane & 3) << 1);
            float2 v0 = make_float2(acc[mi][ni][0], acc[mi][ni][1]);
            float2 v1 = make_float2(acc[mi][ni][2], acc[mi][ni][3]);
            *(float2*)(C + (size_t)row * D_MODEL + col)       = v0;
            *(float2*)(C + (size_t)(row + 8) * D_MODEL + col) = v1;
        }
    }
}

__global__ void __launch_bounds__(256, 2)
qkv_proj_kernel(const float* __restrict__ q_in,
                const float* __restrict__ k_in,
                const float* __restrict__ v_in,
                const float* __restrict__ Wq,
                const float* __restrict__ Wk,
                const float* __restrict__ Wv)
{
    const int z = blockIdx.z;
    const float* A = (z == 0) ? q_in : (z == 1) ? k_in : v_in;
    const float* W = (z == 0) ? Wq   : (z == 1) ? Wk   : Wv;
    float*       C = (z == 0) ? g_Q  : (z == 1) ? g_K  : g_V;
    gemm_tf32(A, W, C);
}

__global__ void __launch_bounds__(256, 2)
oproj_kernel(const float* __restrict__ Wo, float* __restrict__ out)
{
    gemm_tf32(g_ctx, Wo, out);
}

// ---------------------------------------------------------------------------
// Flash attention (tensor cores, pipelined).
// 128 threads (4 warps), 128 q-rows/block; warp w owns rows [32w,32w+32).
// Q lives in registers (warp-private fragments, pre-scaled by 1/8).
// K/V double-buffered fp32 via cp.async, tf32 cvt at fragment load.
// P routed through smem in tf32 (warp-private rows -> __syncwarp only).
// Smem words: Ps 128x68 | K 2x64x68 | V 2x64x72  = 26624 (106.5 KB)
// ---------------------------------------------------------------------------
#define APAD 68
#define VPAD 72
#define P_OFF 0
#define K_OFF (128 * APAD)
#define V_OFF (128 * APAD + 2 * 64 * APAD)
#define ATTN_SMEM_BYTES ((128 * APAD + 2 * 64 * APAD + 2 * 64 * VPAD) * 4)

__device__ __forceinline__ void attn_stage(float* Kd, float* Vd,
                                           const float* __restrict__ Kg,
                                           const float* __restrict__ Vg,
                                           int kt, int tid)
{
#pragma unroll
    for (int u = 0; u < 8; u++) {
        int idx = tid + (u << 7);
        int r = idx >> 4;
        int c = (idx & 15) << 2;
        cp16(&Kd[r * APAD + c], Kg + (size_t)(kt + r) * D_MODEL + c);
        cp16(&Vd[r * VPAD + c], Vg + (size_t)(kt + r) * D_MODEL + c);
    }
    cp_commit();
}

__global__ void __launch_bounds__(128, 2)
attn_kernel()
{
    const int tid  = threadIdx.x;
    const int lane = tid & 31;
    const int warp = tid >> 5;
    const int bh   = blockIdx.y;
    const int b    = bh / NHEAD;
    const int h    = bh % NHEAD;
    const int q0   = blockIdx.x * 128;

    unsigned* Ps = (unsigned*)dynsm + P_OFF;
    float*    Ks = (float*)dynsm + K_OFF;
    float*    Vs = (float*)dynsm + V_OFF;

    const float* Qg = g_Q + (size_t)(b * SEQ + q0) * D_MODEL + h * DK;
    const float* Kg = g_K + (size_t)(b * SEQ) * D_MODEL + h * DK;
    const float* Vg = g_V + (size_t)(b * SEQ) * D_MODEL + h * DK;

    const int wrow = warp << 5;   // warp's base q-row in tile

    // Kick off first K/V stage, then load Q fragments (overlaps with cp.async).
    attn_stage(Ks, Vs, Kg, Vg, 0, tid);

    unsigned q[2][8][4];
#pragma unroll
    for (int mi = 0; mi < 2; mi++) {
#pragma unroll
        for (int ks = 0; ks < 8; ks++) {
            const float* qp = Qg + (size_t)(wrow + (mi << 4) + (lane >> 2)) * D_MODEL
                                 + (ks << 3) + (lane & 3);
            q[mi][ks][0] = f2tf(0.125f * qp[0]);
            q[mi][ks][1] = f2tf(0.125f * qp[8 * D_MODEL]);
            q[mi][ks][2] = f2tf(0.125f * qp[4]);
            q[mi][ks][3] = f2tf(0.125f * qp[8 * D_MODEL + 4]);
        }
    }

    float o[2][8][4];
    float mrow[2][2], lrow[2][2];
#pragma unroll
    for (int mi = 0; mi < 2; mi++) {
        mrow[mi][0] = -1e30f; mrow[mi][1] = -1e30f;
        lrow[mi][0] = 0.0f;   lrow[mi][1] = 0.0f;
#pragma unroll
        for (int nt = 0; nt < 8; nt++)
#pragma unroll
            for (int r = 0; r < 4; r++) o[mi][nt][r] = 0.0f;
    }

    const int NT = SEQ / 64;   // 32
    for (int t = 0; t < NT; t++) {
        cp_wait<0>();
        __syncthreads();
        if (t + 1 < NT)
            attn_stage(Ks + ((t + 1) & 1) * 64 * APAD,
                       Vs + ((t + 1) & 1) * 64 * VPAD,
                       Kg, Vg, (t + 1) * 64, tid);

        const float* Kb = Ks + (t & 1) * 64 * APAD;
        const float* Vb = Vs + (t & 1) * 64 * VPAD;

        // S = Q K^T
        float s[2][8][4];
#pragma unroll
        for (int mi = 0; mi < 2; mi++)
#pragma unroll
            for (int nt = 0; nt < 8; nt++)
#pragma unroll
                for (int r = 0; r < 4; r++) s[mi][nt][r] = 0.0f;

#pragma unroll
        for (int ks = 0; ks < 8; ks++) {
            const int kk = (ks << 3) + (lane & 3);
#pragma unroll
            for (int nt = 0; nt < 8; nt++) {
                int key = (nt << 3) + (lane >> 2);
                unsigned bb[2];
                bb[0] = f2tf(Kb[key * APAD + kk]);
                bb[1] = f2tf(Kb[key * APAD + kk + 4]);
                mma_tf32(s[0][nt], q[0][ks], bb);
                mma_tf32(s[1][nt], q[1][ks], bb);
            }
        }

        // Online softmax
#pragma unroll
        for (int mi = 0; mi < 2; mi++) {
#pragma unroll
            for (int rr = 0; rr < 2; rr++) {
                float mx = -1e30f;
#pragma unroll
                for (int nt = 0; nt < 8; nt++) {
                    mx = fmaxf(mx, s[mi][nt][2 * rr]);
                    mx = fmaxf(mx, s[mi][nt][2 * rr + 1]);
                }
                mx = fmaxf(mx, __shfl_xor_sync(0xffffffffu, mx, 1));
                mx = fmaxf(mx, __shfl_xor_sync(0xffffffffu, mx, 2));
                float mnew = fmaxf(mrow[mi][rr], mx);
                float corr = __expf(mrow[mi][rr] - mnew);
                float sum = 0.0f;
#pragma unroll
                for (int nt = 0; nt < 8; nt++) {
                    float p0 = __expf(s[mi][nt][2 * rr]     - mnew);
                    float p1 = __expf(s[mi][nt][2 * rr + 1] - mnew);
                    s[mi][nt][2 * rr]     = p0;
                    s[mi][nt][2 * rr + 1] = p1;
                    sum += p0 + p1;
                }
                sum += __shfl_xor_sync(0xffffffffu, sum, 1);
                sum += __shfl_xor_sync(0xffffffffu, sum, 2);
                lrow[mi][rr] = lrow[mi][rr] * corr + sum;
                mrow[mi][rr] = mnew;
#pragma unroll
                for (int nt = 0; nt < 8; nt++) {
                    o[mi][nt][2 * rr]     *= corr;
                    o[mi][nt][2 * rr + 1] *= corr;
                }
            }
        }

        // P -> smem (tf32, warp-private rows)
#pragma unroll
        for (int mi = 0; mi < 2; mi++) {
            int row = wrow + (mi << 4) + (lane >> 2);
#pragma unroll
            for (int nt = 0; nt < 8; nt++) {
                int col = (nt << 3) + ((lane & 3) << 1);
                Ps[row * APAD + col]           = f2tf(s[mi][nt][0]);
                Ps[row * APAD + col + 1]       = f2tf(s[mi][nt][1]);
                Ps[(row + 8) * APAD + col]     = f2tf(s[mi][nt][2]);
                Ps[(row + 8) * APAD + col + 1] = f2tf(s[mi][nt][3]);
            }
        }
        __syncwarp();

        // O += P V
#pragma unroll
        for (int ks = 0; ks < 8; ks++) {
            const int kk = (ks << 3) + (lane & 3);
            unsigned a[2][4];
#pragma unroll
            for (int mi = 0; mi < 2; mi++) {
                int row = wrow + (mi << 4) + (lane >> 2);
                a[mi][0] = Ps[row * APAD + kk];
                a[mi][1] = Ps[(row + 8) * APAD + kk];
                a[mi][2] = Ps[row * APAD + kk + 4];
                a[mi][3] = Ps[(row + 8) * APAD + kk + 4];
            }
#pragma unroll
            for (int nt = 0; nt < 8; nt++) {
                int dcol = (nt << 3) + (lane >> 2);
                unsigned bb[2];
                bb[0] = f2tf(Vb[kk * VPAD + dcol]);
                bb[1] = f2tf(Vb[(kk + 4) * VPAD + dcol]);
                mma_tf32(o[0][nt], a[0], bb);
                mma_tf32(o[1][nt], a[1], bb);
            }
        }
    }

    // Epilogue
    float* Cg = g_ctx + (size_t)(b * SEQ + q0) * D_MODEL + h * DK;
#pragma unroll
    for (int mi = 0; mi < 2; mi++) {
        int row = wrow + (mi << 4) + (lane >> 2);
        float inv0 = 1.0f / lrow[mi][0];
        float inv1 = 1.0f / lrow[mi][1];
#pragma unroll
        for (int nt = 0; nt < 8; nt++) {
            int col = (nt << 3) + ((lane & 3) << 1);
            float2 v0 = make_float2(o[mi][nt][0] * inv0, o[mi][nt][1] * inv0);
            float2 v1 = make_float2(o[mi][nt][2] * inv1, o[mi][nt][3] * inv1);
            *(float2*)(Cg + (size_t)row * D_MODEL + col)       = v0;
            *(float2*)(Cg + (size_t)(row + 8) * D_MODEL + col) = v1;
        }
    }
}

// ---------------------------------------------------------------------------
extern "C" void kernel_launch(void* const* d_in, const int* in_sizes, int n_in,
                              void* d_out, int out_size)
{
    const float* query  = (const float*)d_in[0];
    const float* key_in = (const float*)d_in[1];
    const float* value  = (const float*)d_in[2];
    const float* Wq     = (const float*)d_in[3];
    const float* Wk     = (const float*)d_in[4];
    const float* Wv     = (const float*)d_in[5];
    const float* Wo     = (const float*)d_in[6];
    float* out = (float*)d_out;

    static int attr_done = 0;
    if (!attr_done) {
        cudaFuncSetAttribute(qkv_proj_kernel,
                             cudaFuncAttributeMaxDynamicSharedMemorySize, GEMM_SMEM_BYTES);
        cudaFuncSetAttribute(oproj_kernel,
                             cudaFuncAttributeMaxDynamicSharedMemorySize, GEMM_SMEM_BYTES);
        cudaFuncSetAttribute(attn_kernel,
                             cudaFuncAttributeMaxDynamicSharedMemorySize, ATTN_SMEM_BYTES);
        attr_done = 1;
    }

    dim3 gproj(D_MODEL / 128, MTOT / 128, 3);
    qkv_proj_kernel<<<gproj, 256, GEMM_SMEM_BYTES>>>(query, key_in, value, Wq, Wk, Wv);

    dim3 gattn(SEQ / 128, BATCH * NHEAD);
    attn_kernel<<<gattn, 128, ATTN_SMEM_BYTES>>>();

    dim3 gout(D_MODEL / 128, MTOT / 128);
    oproj_kernel<<<gout, 256, GEMM_SMEM_BYTES>>>(Wo, out);
}

// round 5
// speedup vs baseline: 1.5090x; 1.5090x over previous
#include <cuda_runtime.h>
#include <cuda_fp16.h>

#define D_MODEL 768
#define SEQ     2048
#define BATCH   2
#define NHEAD   12
#define DK      64
#define MTOT    (BATCH*SEQ)   /* 4096 */
#define NIN     (MTOT*D_MODEL)
#define NW      (D_MODEL*D_MODEL)

// fp16 copies of inputs + intermediates (no cudaMalloc allowed)
__device__ __half g_qin[NIN], g_kin[NIN], g_vin[NIN];
__device__ __half g_wq[NW], g_wk[NW], g_wv[NW], g_wo[NW];
__device__ __half g_Qh[NIN], g_Kh[NIN], g_Vh[NIN], g_ctxh[NIN];

extern __shared__ unsigned char dynsm[];

// ---------------------------------------------------------------------------
// helpers
// ---------------------------------------------------------------------------
__device__ __forceinline__ void mma16(float d[4], const unsigned a[4], const unsigned b[2]) {
    asm volatile(
        "mma.sync.aligned.m16n8k16.row.col.f32.f16.f16.f32 "
        "{%0,%1,%2,%3},{%4,%5,%6,%7},{%8,%9},{%0,%1,%2,%3};"
        : "+f"(d[0]), "+f"(d[1]), "+f"(d[2]), "+f"(d[3])
        : "r"(a[0]), "r"(a[1]), "r"(a[2]), "r"(a[3]),
          "r"(b[0]), "r"(b[1]));
}
__device__ __forceinline__ unsigned ld32(const __half* p) {
    return *(const unsigned*)p;
}
__device__ __forceinline__ void cp16(void* dst, const void* src) {
    unsigned d = (unsigned)__cvta_generic_to_shared(dst);
    asm volatile("cp.async.cg.shared.global [%0], [%1], 16;\n" :: "r"(d), "l"(src));
}
__device__ __forceinline__ void cp_commit() {
    asm volatile("cp.async.commit_group;\n" ::: "memory");
}
template <int N>
__device__ __forceinline__ void cp_wait() {
    asm volatile("cp.async.wait_group %0;\n" :: "n"(N) : "memory");
}
__device__ __forceinline__ void ldm_x4_t(unsigned& r0, unsigned& r1,
                                         unsigned& r2, unsigned& r3, const __half* p) {
    unsigned a = (unsigned)__cvta_generic_to_shared(p);
    asm volatile("ldmatrix.sync.aligned.m8n8.x4.trans.shared.b16 {%0,%1,%2,%3}, [%4];"
                 : "=r"(r0), "=r"(r1), "=r"(r2), "=r"(r3) : "r"(a));
}

// ---------------------------------------------------------------------------
// fp32 -> fp16 conversion pre-pass (7 arrays via blockIdx.y)
// ---------------------------------------------------------------------------
__global__ void __launch_bounds__(256)
cvt_kernel(const float* q, const float* k, const float* v,
           const float* wq, const float* wk, const float* wv, const float* wo)
{
    const int y = blockIdx.y;
    const float* src;
    __half* dst;
    int n;
    switch (y) {
        case 0: src = q;  dst = g_qin; n = NIN; break;
        case 1: src = k;  dst = g_kin; n = NIN; break;
        case 2: src = v;  dst = g_vin; n = NIN; break;
        case 3: src = wq; dst = g_wq;  n = NW;  break;
        case 4: src = wk; dst = g_wk;  n = NW;  break;
        case 5: src = wv; dst = g_wv;  n = NW;  break;
        default: src = wo; dst = g_wo; n = NW;  break;
    }
    int i = (blockIdx.x * 256 + threadIdx.x) * 4;
    if (i >= n) return;
    float4 f = *(const float4*)(src + i);
    __half2* d2 = (__half2*)(dst + i);
    d2[0] = __floats2half2_rn(f.x, f.y);
    d2[1] = __floats2half2_rn(f.z, f.w);
}

// ---------------------------------------------------------------------------
// fp16 GEMM: C[M,N] = A[M,768] @ W[N,768]^T, tile 128x128x32, 8 warps,
// cp.async double-buffered. Warp tile 64x32 = 4x4 m16n8k16.
// Smem rows padded to 40 halves -> all fragment LDS conflict-free.
// ---------------------------------------------------------------------------
#define HPAD 40
#define HBUF (128 * HPAD)                       /* halves per operand buf */
#define GEMM_SMEM_BYTES (4 * HBUF * 2)          /* 40960 B */

__device__ __forceinline__ void gemm_stage(__half* Ad, __half* Wd,
                                           const __half* __restrict__ A,
                                           const __half* __restrict__ W,
                                           int bm, int bn, int k0, int tid)
{
#pragma unroll
    for (int u = 0; u < 2; u++) {
        int idx = tid + (u << 8);
        int r = idx >> 2;
        int c = (idx & 3) << 3;
        cp16(&Ad[r * HPAD + c], A + (size_t)(bm + r) * D_MODEL + k0 + c);
        cp16(&Wd[r * HPAD + c], W + (size_t)(bn + r) * D_MODEL + k0 + c);
    }
    cp_commit();
}

__device__ __forceinline__ void gemm_fp16(const __half* __restrict__ A,
                                          const __half* __restrict__ W,
                                          __half* __restrict__ Ch,
                                          float* __restrict__ Cf,
                                          float scale)
{
    __half* As = (__half*)dynsm;            // 2 x HBUF
    __half* Ws = (__half*)dynsm + 2 * HBUF * 2 / 2;  // after As bufs
    Ws = (__half*)dynsm + 2 * HBUF;

    const int tid  = threadIdx.x;
    const int lane = tid & 31;
    const int warp = tid >> 5;
    const int wm   = (warp >> 2) * 64;
    const int wn   = (warp & 3) * 32;
    const int bm   = blockIdx.y * 128;
    const int bn   = blockIdx.x * 128;

    float acc[4][4][4];
#pragma unroll
    for (int mi = 0; mi < 4; mi++)
#pragma unroll
        for (int ni = 0; ni < 4; ni++)
#pragma unroll
            for (int r = 0; r < 4; r++) acc[mi][ni][r] = 0.0f;

    gemm_stage(As, Ws, A, W, bm, bn, 0, tid);

    const int NT = D_MODEL / 32;   // 24
    for (int t = 0; t < NT; t++) {
        cp_wait<0>();
        __syncthreads();
        if (t + 1 < NT)
            gemm_stage(As + ((t + 1) & 1) * HBUF, Ws + ((t + 1) & 1) * HBUF,
                       A, W, bm, bn, (t + 1) * 32, tid);

        const __half* Ab = As + (t & 1) * HBUF;
        const __half* Wb = Ws + (t & 1) * HBUF;

#pragma unroll
        for (int ks = 0; ks < 2; ks++) {
            const int kcol = (ks << 4) + ((lane & 3) << 1);
            unsigned a[4][4], b[4][2];
#pragma unroll
            for (int mi = 0; mi < 4; mi++) {
                const __half* ap = Ab + (wm + (mi << 4) + (lane >> 2)) * HPAD + kcol;
                a[mi][0] = ld32(ap);
                a[mi][1] = ld32(ap + 8 * HPAD);
                a[mi][2] = ld32(ap + 8);
                a[mi][3] = ld32(ap + 8 * HPAD + 8);
            }
#pragma unroll
            for (int ni = 0; ni < 4; ni++) {
                const __half* bp = Wb + (wn + (ni << 3) + (lane >> 2)) * HPAD + kcol;
                b[ni][0] = ld32(bp);
                b[ni][1] = ld32(bp + 8);
            }
#pragma unroll
            for (int mi = 0; mi < 4; mi++)
#pragma unroll
                for (int ni = 0; ni < 4; ni++)
                    mma16(acc[mi][ni], a[mi], b[ni]);
        }
    }

    // epilogue
#pragma unroll
    for (int mi = 0; mi < 4; mi++) {
#pragma unroll
        for (int ni = 0; ni < 4; ni++) {
            int row = bm + wm + (mi << 4) + (lane >> 2);
            int col = bn + wn + (ni << 3) + ((lane & 3) << 1);
            if (Ch) {
                *(__half2*)(Ch + (size_t)row * D_MODEL + col) =
                    __floats2half2_rn(acc[mi][ni][0] * scale, acc[mi][ni][1] * scale);
                *(__half2*)(Ch + (size_t)(row + 8) * D_MODEL + col) =
                    __floats2half2_rn(acc[mi][ni][2] * scale, acc[mi][ni][3] * scale);
            } else {
                *(float2*)(Cf + (size_t)row * D_MODEL + col) =
                    make_float2(acc[mi][ni][0], acc[mi][ni][1]);
                *(float2*)(Cf + (size_t)(row + 8) * D_MODEL + col) =
                    make_float2(acc[mi][ni][2], acc[mi][ni][3]);
            }
        }
    }
}

__global__ void __launch_bounds__(256, 2)
qkv_proj_kernel()
{
    const int z = blockIdx.z;
    const __half* A = (z == 0) ? g_qin : (z == 1) ? g_kin : g_vin;
    const __half* W = (z == 0) ? g_wq  : (z == 1) ? g_wk  : g_wv;
    __half*       C = (z == 0) ? g_Qh  : (z == 1) ? g_Kh  : g_Vh;
    float scale = (z == 0) ? 0.125f : 1.0f;   // fold 1/sqrt(Dk) into Q
    gemm_fp16(A, W, C, nullptr, scale);
}

__global__ void __launch_bounds__(256, 2)
oproj_kernel(float* __restrict__ out)
{
    gemm_fp16(g_ctxh, g_wo, nullptr, out, 1.0f);
}

// ---------------------------------------------------------------------------
// fp16 flash attention. 128 threads (4 warps), 128 q-rows/block, 64-key tiles.
// Q/K/P fragments: manual conflict-free LDS (pad 72 halves).
// V B-fragments: ldmatrix.x4.trans on natural [key][d] layout.
// Smem halves: Qs 128x72 | Ps 128x72 | Ks 64x72 | Vs 64x72 = 55296 B
// ---------------------------------------------------------------------------
#define ATP 72
#define ATTN_SMEM_BYTES ((128*ATP + 128*ATP + 64*ATP + 64*ATP) * 2)

__global__ void __launch_bounds__(128, 2)
attn_kernel()
{
    const int tid  = threadIdx.x;
    const int lane = tid & 31;
    const int warp = tid >> 5;
    const int bh   = blockIdx.y;
    const int b    = bh / NHEAD;
    const int h    = bh % NHEAD;
    const int q0   = blockIdx.x * 128;

    __half* Qs = (__half*)dynsm;
    __half* Ps = Qs + 128 * ATP;
    __half* Ks = Qs + 2 * 128 * ATP;
    __half* Vs = Ks + 64 * ATP;

    const __half* Qg = g_Qh + (size_t)(b * SEQ + q0) * D_MODEL + h * DK;
    const __half* Kg = g_Kh + (size_t)(b * SEQ) * D_MODEL + h * DK;
    const __half* Vg = g_Vh + (size_t)(b * SEQ) * D_MODEL + h * DK;

    // Load Q tile (already scaled by 1/8 in projection): 128x64 halves
#pragma unroll
    for (int u = 0; u < 8; u++) {
        int idx = tid + (u << 7);
        int r = idx >> 3;
        int c = (idx & 7) << 3;
        *(uint4*)&Qs[r * ATP + c] = *(const uint4*)(Qg + (size_t)r * D_MODEL + c);
    }

    float o[2][8][4];
    float mrow[2][2], lrow[2][2];
#pragma unroll
    for (int mi = 0; mi < 2; mi++) {
        mrow[mi][0] = -1e30f; mrow[mi][1] = -1e30f;
        lrow[mi][0] = 0.0f;   lrow[mi][1] = 0.0f;
#pragma unroll
        for (int nt = 0; nt < 8; nt++)
#pragma unroll
            for (int r = 0; r < 4; r++) o[mi][nt][r] = 0.0f;
    }

    const int wrow = warp << 5;

    for (int kt = 0; kt < SEQ; kt += 64) {
        __syncthreads();
#pragma unroll
        for (int u = 0; u < 4; u++) {
            int idx = tid + (u << 7);
            int r = idx >> 3;
            int c = (idx & 7) << 3;
            *(uint4*)&Ks[r * ATP + c] = *(const uint4*)(Kg + (size_t)(kt + r) * D_MODEL + c);
            *(uint4*)&Vs[r * ATP + c] = *(const uint4*)(Vg + (size_t)(kt + r) * D_MODEL + c);
        }
        __syncthreads();

        // S = Q K^T (k-dim = d, 4 k16 steps)
        float s[2][8][4];
#pragma unroll
        for (int mi = 0; mi < 2; mi++)
#pragma unroll
            for (int nt = 0; nt < 8; nt++)
#pragma unroll
                for (int r = 0; r < 4; r++) s[mi][nt][r] = 0.0f;

#pragma unroll
        for (int ks = 0; ks < 4; ks++) {
            const int kcol = (ks << 4) + ((lane & 3) << 1);
            unsigned a[2][4];
#pragma unroll
            for (int mi = 0; mi < 2; mi++) {
                const __half* ap = Qs + (wrow + (mi << 4) + (lane >> 2)) * ATP + kcol;
                a[mi][0] = ld32(ap);
                a[mi][1] = ld32(ap + 8 * ATP);
                a[mi][2] = ld32(ap + 8);
                a[mi][3] = ld32(ap + 8 * ATP + 8);
            }
#pragma unroll
            for (int nt = 0; nt < 8; nt++) {
                const __half* bp = Ks + ((nt << 3) + (lane >> 2)) * ATP + kcol;
                unsigned bb[2];
                bb[0] = ld32(bp);
                bb[1] = ld32(bp + 8);
                mma16(s[0][nt], a[0], bb);
                mma16(s[1][nt], a[1], bb);
            }
        }

        // Online softmax (C-fragment row ownership identical to tf32 version)
#pragma unroll
        for (int mi = 0; mi < 2; mi++) {
#pragma unroll
            for (int rr = 0; rr < 2; rr++) {
                float mx = -1e30f;
#pragma unroll
                for (int nt = 0; nt < 8; nt++) {
                    mx = fmaxf(mx, s[mi][nt][2 * rr]);
                    mx = fmaxf(mx, s[mi][nt][2 * rr + 1]);
                }
                mx = fmaxf(mx, __shfl_xor_sync(0xffffffffu, mx, 1));
                mx = fmaxf(mx, __shfl_xor_sync(0xffffffffu, mx, 2));
                float mnew = fmaxf(mrow[mi][rr], mx);
                float corr = __expf(mrow[mi][rr] - mnew);
                float sum = 0.0f;
#pragma unroll
                for (int nt = 0; nt < 8; nt++) {
                    float p0 = __expf(s[mi][nt][2 * rr]     - mnew);
                    float p1 = __expf(s[mi][nt][2 * rr + 1] - mnew);
                    s[mi][nt][2 * rr]     = p0;
                    s[mi][nt][2 * rr + 1] = p1;
                    sum += p0 + p1;
                }
                sum += __shfl_xor_sync(0xffffffffu, sum, 1);
                sum += __shfl_xor_sync(0xffffffffu, sum, 2);
                lrow[mi][rr] = lrow[mi][rr] * corr + sum;
                mrow[mi][rr] = mnew;
#pragma unroll
                for (int nt = 0; nt < 8; nt++) {
                    o[mi][nt][2 * rr]     *= corr;
                    o[mi][nt][2 * rr + 1] *= corr;
                }
            }
        }

        // P -> smem (half2, warp-private rows)
#pragma unroll
        for (int mi = 0; mi < 2; mi++) {
            int row = wrow + (mi << 4) + (lane >> 2);
#pragma unroll
            for (int nt = 0; nt < 8; nt++) {
                int col = (nt << 3) + ((lane & 3) << 1);
                *(__half2*)&Ps[row * ATP + col] =
                    __floats2half2_rn(s[mi][nt][0], s[mi][nt][1]);
                *(__half2*)&Ps[(row + 8) * ATP + col] =
                    __floats2half2_rn(s[mi][nt][2], s[mi][nt][3]);
            }
        }
        __syncwarp();

        // O += P V  (k-dim = key; V B-frags via ldmatrix.trans)
#pragma unroll
        for (int ks = 0; ks < 4; ks++) {
            const int kcol = (ks << 4) + ((lane & 3) << 1);
            unsigned a[2][4];
#pragma unroll
            for (int mi = 0; mi < 2; mi++) {
                const __half* ap = Ps + (wrow + (mi << 4) + (lane >> 2)) * ATP + kcol;
                a[mi][0] = ld32(ap);
                a[mi][1] = ld32(ap + 8 * ATP);
                a[mi][2] = ld32(ap + 8);
                a[mi][3] = ld32(ap + 8 * ATP + 8);
            }
#pragma unroll
            for (int nt2 = 0; nt2 < 4; nt2++) {
                int row = (ks << 4) + (lane & 15);
                int col = (nt2 << 4) + ((lane & 16) >> 1);
                unsigned r0, r1, r2, r3;
                ldm_x4_t(r0, r1, r2, r3, Vs + row * ATP + col);
                unsigned b0[2] = {r0, r1};
                unsigned b1[2] = {r2, r3};
                mma16(o[0][2 * nt2],     a[0], b0);
                mma16(o[1][2 * nt2],     a[1], b0);
                mma16(o[0][2 * nt2 + 1], a[0], b1);
                mma16(o[1][2 * nt2 + 1], a[1], b1);
            }
        }
    }

    // Epilogue: normalize, write fp16 context (head h columns)
    __half* Cg = g_ctxh + (size_t)(b * SEQ + q0) * D_MODEL + h * DK;
#pragma unroll
    for (int mi = 0; mi < 2; mi++) {
        int row = wrow + (mi << 4) + (lane >> 2);
        float inv0 = 1.0f / lrow[mi][0];
        float inv1 = 1.0f / lrow[mi][1];
#pragma unroll
        for (int nt = 0; nt < 8; nt++) {
            int col = (nt << 3) + ((lane & 3) << 1);
            *(__half2*)(Cg + (size_t)row * D_MODEL + col) =
                __floats2half2_rn(o[mi][nt][0] * inv0, o[mi][nt][1] * inv0);
            *(__half2*)(Cg + (size_t)(row + 8) * D_MODEL + col) =
                __floats2half2_rn(o[mi][nt][2] * inv1, o[mi][nt][3] * inv1);
        }
    }
}

// ---------------------------------------------------------------------------
extern "C" void kernel_launch(void* const* d_in, const int* in_sizes, int n_in,
                              void* d_out, int out_size)
{
    const float* query  = (const float*)d_in[0];
    const float* key_in = (const float*)d_in[1];
    const float* value  = (const float*)d_in[2];
    const float* Wq     = (const float*)d_in[3];
    const float* Wk     = (const float*)d_in[4];
    const float* Wv     = (const float*)d_in[5];
    const float* Wo     = (const float*)d_in[6];
    float* out = (float*)d_out;

    cudaFuncSetAttribute(attn_kernel,
                         cudaFuncAttributeMaxDynamicSharedMemorySize, ATTN_SMEM_BYTES);

    // fp32 -> fp16 pre-pass
    dim3 gcvt((NIN / 4 + 255) / 256, 7);
    cvt_kernel<<<gcvt, 256>>>(query, key_in, value, Wq, Wk, Wv, Wo);

    // Q/K/V projections
    dim3 gproj(D_MODEL / 128, MTOT / 128, 3);
    qkv_proj_kernel<<<gproj, 256, GEMM_SMEM_BYTES>>>();

    // Flash attention
    dim3 gattn(SEQ / 128, BATCH * NHEAD);
    attn_kernel<<<gattn, 128, ATTN_SMEM_BYTES>>>();

    // Output projection (fp32 out)
    dim3 gout(D_MODEL / 128, MTOT / 128);
    oproj_kernel<<<gout, 256, GEMM_SMEM_BYTES>>>(out);
}

// round 6
// speedup vs baseline: 1.8473x; 1.2242x over previous
#include <cuda_runtime.h>
#include <cuda_fp16.h>

#define D_MODEL 768
#define SEQ     2048
#define BATCH   2
#define NHEAD   12
#define DK      64
#define MTOT    (BATCH*SEQ)   /* 4096 */
#define NIN     (MTOT*D_MODEL)
#define NW      (D_MODEL*D_MODEL)

// fp16 copies of inputs + intermediates (no cudaMalloc allowed)
__device__ __half g_qin[NIN], g_kin[NIN], g_vin[NIN];
__device__ __half g_wq[NW], g_wk[NW], g_wv[NW], g_wo[NW];
__device__ __half g_Qh[NIN], g_Kh[NIN], g_Vh[NIN], g_ctxh[NIN];

extern __shared__ unsigned char dynsm[];

// ---------------------------------------------------------------------------
// helpers
// ---------------------------------------------------------------------------
__device__ __forceinline__ void mma16(float d[4], const unsigned a[4], const unsigned b[2]) {
    asm volatile(
        "mma.sync.aligned.m16n8k16.row.col.f32.f16.f16.f32 "
        "{%0,%1,%2,%3},{%4,%5,%6,%7},{%8,%9},{%0,%1,%2,%3};"
        : "+f"(d[0]), "+f"(d[1]), "+f"(d[2]), "+f"(d[3])
        : "r"(a[0]), "r"(a[1]), "r"(a[2]), "r"(a[3]),
          "r"(b[0]), "r"(b[1]));
}
__device__ __forceinline__ unsigned ld32(const __half* p) {
    return *(const unsigned*)p;
}
__device__ __forceinline__ float ex2(float x) {
    float r;
    asm("ex2.approx.f32 %0, %1;" : "=f"(r) : "f"(x));
    return r;
}
__device__ __forceinline__ void cp16(void* dst, const void* src) {
    unsigned d = (unsigned)__cvta_generic_to_shared(dst);
    asm volatile("cp.async.cg.shared.global [%0], [%1], 16;\n" :: "r"(d), "l"(src));
}
__device__ __forceinline__ void cp_commit() {
    asm volatile("cp.async.commit_group;\n" ::: "memory");
}
template <int N>
__device__ __forceinline__ void cp_wait() {
    asm volatile("cp.async.wait_group %0;\n" :: "n"(N) : "memory");
}
__device__ __forceinline__ void ldm_x4_t(unsigned& r0, unsigned& r1,
                                         unsigned& r2, unsigned& r3, const __half* p) {
    unsigned a = (unsigned)__cvta_generic_to_shared(p);
    asm volatile("ldmatrix.sync.aligned.m8n8.x4.trans.shared.b16 {%0,%1,%2,%3}, [%4];"
                 : "=r"(r0), "=r"(r1), "=r"(r2), "=r"(r3) : "r"(a));
}

#define LOG2E 1.4426950408889634f

// ---------------------------------------------------------------------------
// fp32 -> fp16 conversion pre-pass (7 arrays via blockIdx.y)
// ---------------------------------------------------------------------------
__global__ void __launch_bounds__(256)
cvt_kernel(const float* q, const float* k, const float* v,
           const float* wq, const float* wk, const float* wv, const float* wo)
{
    const int y = blockIdx.y;
    const float* src;
    __half* dst;
    int n;
    switch (y) {
        case 0: src = q;  dst = g_qin; n = NIN; break;
        case 1: src = k;  dst = g_kin; n = NIN; break;
        case 2: src = v;  dst = g_vin; n = NIN; break;
        case 3: src = wq; dst = g_wq;  n = NW;  break;
        case 4: src = wk; dst = g_wk;  n = NW;  break;
        case 5: src = wv; dst = g_wv;  n = NW;  break;
        default: src = wo; dst = g_wo; n = NW;  break;
    }
    int i = (blockIdx.x * 256 + threadIdx.x) * 4;
    if (i >= n) return;
    float4 f = *(const float4*)(src + i);
    __half2* d2 = (__half2*)(dst + i);
    d2[0] = __floats2half2_rn(f.x, f.y);
    d2[1] = __floats2half2_rn(f.z, f.w);
}

// ---------------------------------------------------------------------------
// fp16 GEMM: C[M,N] = A[M,768] @ W[N,768]^T, tile 128x128x32, 8 warps,
// 3-stage cp.async pipeline. Warp tile 64x32 = 4x4 m16n8k16.
// ---------------------------------------------------------------------------
#define HPAD 40
#define HBUF (128 * HPAD)                       /* halves per operand buf */
#define GEMM_SMEM_BYTES (6 * HBUF * 2)          /* 3 stages x (A+W) = 61440 B */

__device__ __forceinline__ void gemm_stage(__half* Ad, __half* Wd,
                                           const __half* __restrict__ A,
                                           const __half* __restrict__ W,
                                           int bm, int bn, int k0, int tid)
{
#pragma unroll
    for (int u = 0; u < 2; u++) {
        int idx = tid + (u << 8);
        int r = idx >> 2;
        int c = (idx & 3) << 3;
        cp16(&Ad[r * HPAD + c], A + (size_t)(bm + r) * D_MODEL + k0 + c);
        cp16(&Wd[r * HPAD + c], W + (size_t)(bn + r) * D_MODEL + k0 + c);
    }
    cp_commit();
}

__device__ __forceinline__ void gemm_fp16(const __half* __restrict__ A,
                                          const __half* __restrict__ W,
                                          __half* __restrict__ Ch,
                                          float* __restrict__ Cf,
                                          float scale)
{
    __half* As = (__half*)dynsm;             // 3 x HBUF
    __half* Ws = (__half*)dynsm + 3 * HBUF;  // 3 x HBUF

    const int tid  = threadIdx.x;
    const int lane = tid & 31;
    const int warp = tid >> 5;
    const int wm   = (warp >> 2) * 64;
    const int wn   = (warp & 3) * 32;
    const int bm   = blockIdx.y * 128;
    const int bn   = blockIdx.x * 128;

    float acc[4][4][4];
#pragma unroll
    for (int mi = 0; mi < 4; mi++)
#pragma unroll
        for (int ni = 0; ni < 4; ni++)
#pragma unroll
            for (int r = 0; r < 4; r++) acc[mi][ni][r] = 0.0f;

    gemm_stage(As, Ws, A, W, bm, bn, 0, tid);
    gemm_stage(As + HBUF, Ws + HBUF, A, W, bm, bn, 32, tid);

    const int NT = D_MODEL / 32;   // 24
    for (int t = 0; t < NT; t++) {
        if (t + 2 < NT) {
            int s2 = (t + 2) % 3;
            gemm_stage(As + s2 * HBUF, Ws + s2 * HBUF, A, W, bm, bn, (t + 2) * 32, tid);
        }
        cp_wait<2>();
        __syncthreads();

        const __half* Ab = As + (t % 3) * HBUF;
        const __half* Wb = Ws + (t % 3) * HBUF;

#pragma unroll
        for (int ks = 0; ks < 2; ks++) {
            const int kcol = (ks << 4) + ((lane & 3) << 1);
            unsigned a[4][4], b[4][2];
#pragma unroll
            for (int mi = 0; mi < 4; mi++) {
                const __half* ap = Ab + (wm + (mi << 4) + (lane >> 2)) * HPAD + kcol;
                a[mi][0] = ld32(ap);
                a[mi][1] = ld32(ap + 8 * HPAD);
                a[mi][2] = ld32(ap + 8);
                a[mi][3] = ld32(ap + 8 * HPAD + 8);
            }
#pragma unroll
            for (int ni = 0; ni < 4; ni++) {
                const __half* bp = Wb + (wn + (ni << 3) + (lane >> 2)) * HPAD + kcol;
                b[ni][0] = ld32(bp);
                b[ni][1] = ld32(bp + 8);
            }
#pragma unroll
            for (int mi = 0; mi < 4; mi++)
#pragma unroll
                for (int ni = 0; ni < 4; ni++)
                    mma16(acc[mi][ni], a[mi], b[ni]);
        }
        __syncthreads();
    }

    // epilogue
#pragma unroll
    for (int mi = 0; mi < 4; mi++) {
#pragma unroll
        for (int ni = 0; ni < 4; ni++) {
            int row = bm + wm + (mi << 4) + (lane >> 2);
            int col = bn + wn + (ni << 3) + ((lane & 3) << 1);
            if (Ch) {
                *(__half2*)(Ch + (size_t)row * D_MODEL + col) =
                    __floats2half2_rn(acc[mi][ni][0] * scale, acc[mi][ni][1] * scale);
                *(__half2*)(Ch + (size_t)(row + 8) * D_MODEL + col) =
                    __floats2half2_rn(acc[mi][ni][2] * scale, acc[mi][ni][3] * scale);
            } else {
                *(float2*)(Cf + (size_t)row * D_MODEL + col) =
                    make_float2(acc[mi][ni][0], acc[mi][ni][1]);
                *(float2*)(Cf + (size_t)(row + 8) * D_MODEL + col) =
                    make_float2(acc[mi][ni][2], acc[mi][ni][3]);
            }
        }
    }
}

__global__ void __launch_bounds__(256, 2)
qkv_proj_kernel()
{
    const int z = blockIdx.z;
    const __half* A = (z == 0) ? g_qin : (z == 1) ? g_kin : g_vin;
    const __half* W = (z == 0) ? g_wq  : (z == 1) ? g_wk  : g_wv;
    __half*       C = (z == 0) ? g_Qh  : (z == 1) ? g_Kh  : g_Vh;
    // fold 1/sqrt(Dk) AND log2(e) into Q so softmax can use raw ex2
    float scale = (z == 0) ? 0.125f * LOG2E : 1.0f;
    gemm_fp16(A, W, C, nullptr, scale);
}

__global__ void __launch_bounds__(256, 2)
oproj_kernel(float* __restrict__ out)
{
    gemm_fp16(g_ctxh, g_wo, nullptr, out, 1.0f);
}

// ---------------------------------------------------------------------------
// fp16 flash attention. 128 threads (4 warps), 128 q-rows/block.
// K/V double-buffered 64-key tiles via cp.async.
// Scores are in log2 units (Q pre-scaled by 0.125*log2e) -> softmax uses ex2.
// Smem halves: Qs 128x72 | Ps 128x72 | Ks 2x64x72 | Vs 2x64x72 = 73728 B
// ---------------------------------------------------------------------------
#define ATP 72
#define KVBUF (64 * ATP)
#define ATTN_SMEM_BYTES ((2 * 128 * ATP + 4 * KVBUF) * 2)

__device__ __forceinline__ void attn_stage(__half* Kd, __half* Vd,
                                           const __half* __restrict__ Kg,
                                           const __half* __restrict__ Vg,
                                           int kt, int tid)
{
#pragma unroll
    for (int u = 0; u < 4; u++) {
        int idx = tid + (u << 7);
        int r = idx >> 3;
        int c = (idx & 7) << 3;
        cp16(&Kd[r * ATP + c], Kg + (size_t)(kt + r) * D_MODEL + c);
        cp16(&Vd[r * ATP + c], Vg + (size_t)(kt + r) * D_MODEL + c);
    }
    cp_commit();
}

__global__ void __launch_bounds__(128, 2)
attn_kernel()
{
    const int tid  = threadIdx.x;
    const int lane = tid & 31;
    const int warp = tid >> 5;
    const int bh   = blockIdx.y;
    const int b    = bh / NHEAD;
    const int h    = bh % NHEAD;
    const int q0   = blockIdx.x * 128;

    __half* Qs = (__half*)dynsm;
    __half* Ps = Qs + 128 * ATP;
    __half* Ks = Qs + 2 * 128 * ATP;
    __half* Vs = Ks + 2 * KVBUF;

    const __half* Qg = g_Qh + (size_t)(b * SEQ + q0) * D_MODEL + h * DK;
    const __half* Kg = g_Kh + (size_t)(b * SEQ) * D_MODEL + h * DK;
    const __half* Vg = g_Vh + (size_t)(b * SEQ) * D_MODEL + h * DK;

    // Kick off KV stage 0, then load Q (overlaps).
    attn_stage(Ks, Vs, Kg, Vg, 0, tid);

#pragma unroll
    for (int u = 0; u < 8; u++) {
        int idx = tid + (u << 7);
        int r = idx >> 3;
        int c = (idx & 7) << 3;
        *(uint4*)&Qs[r * ATP + c] = *(const uint4*)(Qg + (size_t)r * D_MODEL + c);
    }

    float o[2][8][4];
    float mrow[2][2], lrow[2][2];
#pragma unroll
    for (int mi = 0; mi < 2; mi++) {
        mrow[mi][0] = -1e30f; mrow[mi][1] = -1e30f;
        lrow[mi][0] = 0.0f;   lrow[mi][1] = 0.0f;
#pragma unroll
        for (int nt = 0; nt < 8; nt++)
#pragma unroll
            for (int r = 0; r < 4; r++) o[mi][nt][r] = 0.0f;
    }

    const int wrow = warp << 5;
    const int NT = SEQ / 64;   // 32

    for (int t = 0; t < NT; t++) {
        if (t + 1 < NT)
            attn_stage(Ks + ((t + 1) & 1) * KVBUF, Vs + ((t + 1) & 1) * KVBUF,
                       Kg, Vg, (t + 1) * 64, tid);
        cp_wait<1>();
        __syncthreads();

        const __half* Kb = Ks + (t & 1) * KVBUF;
        const __half* Vb = Vs + (t & 1) * KVBUF;

        // S = Q K^T (k-dim = d, 4 k16 steps); scores already in log2 units
        float s[2][8][4];
#pragma unroll
        for (int mi = 0; mi < 2; mi++)
#pragma unroll
            for (int nt = 0; nt < 8; nt++)
#pragma unroll
                for (int r = 0; r < 4; r++) s[mi][nt][r] = 0.0f;

#pragma unroll
        for (int ks = 0; ks < 4; ks++) {
            const int kcol = (ks << 4) + ((lane & 3) << 1);
            unsigned a[2][4];
#pragma unroll
            for (int mi = 0; mi < 2; mi++) {
                const __half* ap = Qs + (wrow + (mi << 4) + (lane >> 2)) * ATP + kcol;
                a[mi][0] = ld32(ap);
                a[mi][1] = ld32(ap + 8 * ATP);
                a[mi][2] = ld32(ap + 8);
                a[mi][3] = ld32(ap + 8 * ATP + 8);
            }
#pragma unroll
            for (int nt = 0; nt < 8; nt++) {
                const __half* bp = Kb + ((nt << 3) + (lane >> 2)) * ATP + kcol;
                unsigned bb[2];
                bb[0] = ld32(bp);
                bb[1] = ld32(bp + 8);
                mma16(s[0][nt], a[0], bb);
                mma16(s[1][nt], a[1], bb);
            }
        }

        // Online softmax in base-2
#pragma unroll
        for (int mi = 0; mi < 2; mi++) {
#pragma unroll
            for (int rr = 0; rr < 2; rr++) {
                float mx = -1e30f;
#pragma unroll
                for (int nt = 0; nt < 8; nt++) {
                    mx = fmaxf(mx, s[mi][nt][2 * rr]);
                    mx = fmaxf(mx, s[mi][nt][2 * rr + 1]);
                }
                mx = fmaxf(mx, __shfl_xor_sync(0xffffffffu, mx, 1));
                mx = fmaxf(mx, __shfl_xor_sync(0xffffffffu, mx, 2));
                float mnew = fmaxf(mrow[mi][rr], mx);
                float corr = ex2(mrow[mi][rr] - mnew);
                float sum = 0.0f;
#pragma unroll
                for (int nt = 0; nt < 8; nt++) {
                    float p0 = ex2(s[mi][nt][2 * rr]     - mnew);
                    float p1 = ex2(s[mi][nt][2 * rr + 1] - mnew);
                    s[mi][nt][2 * rr]     = p0;
                    s[mi][nt][2 * rr + 1] = p1;
                    sum += p0 + p1;
                }
                sum += __shfl_xor_sync(0xffffffffu, sum, 1);
                sum += __shfl_xor_sync(0xffffffffu, sum, 2);
                lrow[mi][rr] = lrow[mi][rr] * corr + sum;
                mrow[mi][rr] = mnew;
#pragma unroll
                for (int nt = 0; nt < 8; nt++) {
                    o[mi][nt][2 * rr]     *= corr;
                    o[mi][nt][2 * rr + 1] *= corr;
                }
            }
        }

        // P -> smem (half2, warp-private rows)
#pragma unroll
        for (int mi = 0; mi < 2; mi++) {
            int row = wrow + (mi << 4) + (lane >> 2);
#pragma unroll
            for (int nt = 0; nt < 8; nt++) {
                int col = (nt << 3) + ((lane & 3) << 1);
                *(__half2*)&Ps[row * ATP + col] =
                    __floats2half2_rn(s[mi][nt][0], s[mi][nt][1]);
                *(__half2*)&Ps[(row + 8) * ATP + col] =
                    __floats2half2_rn(s[mi][nt][2], s[mi][nt][3]);
            }
        }
        __syncwarp();

        // O += P V  (k-dim = key; V B-frags via ldmatrix.trans)
#pragma unroll
        for (int ks = 0; ks < 4; ks++) {
            const int kcol = (ks << 4) + ((lane & 3) << 1);
            unsigned a[2][4];
#pragma unroll
            for (int mi = 0; mi < 2; mi++) {
                const __half* ap = Ps + (wrow + (mi << 4) + (lane >> 2)) * ATP + kcol;
                a[mi][0] = ld32(ap);
                a[mi][1] = ld32(ap + 8 * ATP);
                a[mi][2] = ld32(ap + 8);
                a[mi][3] = ld32(ap + 8 * ATP + 8);
            }
#pragma unroll
            for (int nt2 = 0; nt2 < 4; nt2++) {
                int row = (ks << 4) + (lane & 15);
                int col = (nt2 << 4) + ((lane & 16) >> 1);
                unsigned r0, r1, r2, r3;
                ldm_x4_t(r0, r1, r2, r3, Vb + row * ATP + col);
                unsigned b0[2] = {r0, r1};
                unsigned b1[2] = {r2, r3};
                mma16(o[0][2 * nt2],     a[0], b0);
                mma16(o[1][2 * nt2],     a[1], b0);
                mma16(o[0][2 * nt2 + 1], a[0], b1);
                mma16(o[1][2 * nt2 + 1], a[1], b1);
            }
        }
        __syncthreads();
    }

    // Epilogue: normalize, write fp16 context (head h columns)
    __half* Cg = g_ctxh + (size_t)(b * SEQ + q0) * D_MODEL + h * DK;
#pragma unroll
    for (int mi = 0; mi < 2; mi++) {
        int row = wrow + (mi << 4) + (lane >> 2);
        float inv0 = 1.0f / lrow[mi][0];
        float inv1 = 1.0f / lrow[mi][1];
#pragma unroll
        for (int nt = 0; nt < 8; nt++) {
            int col = (nt << 3) + ((lane & 3) << 1);
            *(__half2*)(Cg + (size_t)row * D_MODEL + col) =
                __floats2half2_rn(o[mi][nt][0] * inv0, o[mi][nt][1] * inv0);
            *(__half2*)(Cg + (size_t)(row + 8) * D_MODEL + col) =
                __floats2half2_rn(o[mi][nt][2] * inv1, o[mi][nt][3] * inv1);
        }
    }
}

// ---------------------------------------------------------------------------
extern "C" void kernel_launch(void* const* d_in, const int* in_sizes, int n_in,
                              void* d_out, int out_size)
{
    const float* query  = (const float*)d_in[0];
    const float* key_in = (const float*)d_in[1];
    const float* value  = (const float*)d_in[2];
    const float* Wq     = (const float*)d_in[3];
    const float* Wk     = (const float*)d_in[4];
    const float* Wv     = (const float*)d_in[5];
    const float* Wo     = (const float*)d_in[6];
    float* out = (float*)d_out;

    cudaFuncSetAttribute(attn_kernel,
                         cudaFuncAttributeMaxDynamicSharedMemorySize, ATTN_SMEM_BYTES);
    cudaFuncSetAttribute(qkv_proj_kernel,
                         cudaFuncAttributeMaxDynamicSharedMemorySize, GEMM_SMEM_BYTES);
    cudaFuncSetAttribute(oproj_kernel,
                         cudaFuncAttributeMaxDynamicSharedMemorySize, GEMM_SMEM_BYTES);

    // fp32 -> fp16 pre-pass
    dim3 gcvt((NIN / 4 + 255) / 256, 7);
    cvt_kernel<<<gcvt, 256>>>(query, key_in, value, Wq, Wk, Wv, Wo);

    // Q/K/V projections
    dim3 gproj(D_MODEL / 128, MTOT / 128, 3);
    qkv_proj_kernel<<<gproj, 256, GEMM_SMEM_BYTES>>>();

    // Flash attention
    dim3 gattn(SEQ / 128, BATCH * NHEAD);
    attn_kernel<<<gattn, 128, ATTN_SMEM_BYTES>>>();

    // Output projection (fp32 out)
    dim3 gout(D_MODEL / 128, MTOT / 128);
    oproj_kernel<<<gout, 256, GEMM_SMEM_BYTES>>>(out);
}